// round 4
// baseline (speedup 1.0000x reference)
#include <cuda_runtime.h>
#include <cuda_bf16.h>

#define NB 2
#define NN 2048
#define NF 256
#define NH 8
#define NO 32

// ---------------- scratch (device globals; no allocation allowed) -------------
__device__ __align__(128) float    g_h [NB*NN*NF];   // layer input / stage-B output
__device__ __align__(128) float    g_hA[NB*NN*NF];   // stage-A attention output
__device__ __align__(128) float    g_Wh[NB*NN*NF];   // projected features (V)
__device__ __align__(128) float    g_Wc[NF*NF];      // packed per-layer head weights
__device__ __align__(128) float    g_s1[NB*NH*NN];
__device__ __align__(128) float    g_s2[NB*NH*NN];
__device__             float       g_M2[NB*NH];
__device__ __align__(128) unsigned g_bm[NB*NN*(NN/32)];  // adjacency bitmask

// ---------------- adjacency -> bitmask (runs once) ----------------------------
__global__ void bm_kernel(const int* __restrict__ adj) {
    int wid  = blockIdx.x * 8 + (threadIdx.x >> 5);
    int lane = threadIdx.x & 31;
    int word = wid & 63;
    int row  = wid >> 6;                       // b*NN + i
    int j = word * 32 + lane;
    int a = adj[(size_t)row * NN + j];
    unsigned bits = __ballot_sync(0xffffffffu, a != 0);
    if (lane == 0) g_bm[wid] = bits;
}

// ---------------- pack W_heads[l] into [F, H*O] column-major-by-head ----------
__global__ void pack_kernel(const float* __restrict__ Wheads, int l) {
    int f = blockIdx.x, c = threadIdx.x;
    g_Wc[f * NF + c] =
        Wheads[(((size_t)l * NH + (c >> 5)) * NF + f) * NO + (c & 31)];
}

// ---------------- GEMM: g_Wh[M,256] = A[M,256] @ Bm[256,256] ------------------
// asel: 0 -> Aext (x), 1 -> g_h, 2 -> g_hA ; bsel: 0 -> g_Wc, 1 -> Bext
__global__ void gemm_kernel(const float* __restrict__ Aext,
                            const float* __restrict__ Bext,
                            int asel, int bsel) {
    const float* A  = (asel == 0) ? Aext : (asel == 1 ? g_h : g_hA);
    const float* Bm = (bsel == 0) ? g_Wc : Bext;
    __shared__ __align__(16) float Ast[16][68];   // [k][m], padded
    __shared__ __align__(16) float Bs [16][64];   // [k][n]
    int tid = threadIdx.x;
    int tx = tid & 15, ty = tid >> 4;
    int mbase = blockIdx.y * 64, nbase = blockIdx.x * 64;
    float acc[4][4];
    #pragma unroll
    for (int i = 0; i < 4; i++)
        #pragma unroll
        for (int j = 0; j < 4; j++) acc[i][j] = 0.f;

    int am = tid >> 2, ak = (tid & 3) * 4;
    int bk = tid >> 4, bn = (tid & 15) * 4;

    for (int kk = 0; kk < NF; kk += 16) {
        float4 av = *(const float4*)&A [(size_t)(mbase + am) * NF + kk + ak];
        float4 bv = *(const float4*)&Bm[(size_t)(kk + bk) * NF + nbase + bn];
        Ast[ak + 0][am] = av.x; Ast[ak + 1][am] = av.y;
        Ast[ak + 2][am] = av.z; Ast[ak + 3][am] = av.w;
        *(float4*)&Bs[bk][bn] = bv;
        __syncthreads();
        #pragma unroll
        for (int k = 0; k < 16; k++) {
            float4 a = *(const float4*)&Ast[k][ty * 4];
            float4 b = *(const float4*)&Bs [k][tx * 4];
            acc[0][0] += a.x * b.x; acc[0][1] += a.x * b.y;
            acc[0][2] += a.x * b.z; acc[0][3] += a.x * b.w;
            acc[1][0] += a.y * b.x; acc[1][1] += a.y * b.y;
            acc[1][2] += a.y * b.z; acc[1][3] += a.y * b.w;
            acc[2][0] += a.z * b.x; acc[2][1] += a.z * b.y;
            acc[2][2] += a.z * b.z; acc[2][3] += a.z * b.w;
            acc[3][0] += a.w * b.x; acc[3][1] += a.w * b.y;
            acc[3][2] += a.w * b.z; acc[3][3] += a.w * b.w;
        }
        __syncthreads();
    }
    #pragma unroll
    for (int i = 0; i < 4; i++) {
        *(float4*)&g_Wh[(size_t)(mbase + ty * 4 + i) * NF + nbase + tx * 4] =
            make_float4(acc[i][0], acc[i][1], acc[i][2], acc[i][3]);
    }
}

// ---------------- s1/s2 for the 8-head stage ----------------------------------
__global__ void sheads_kernel(const float* __restrict__ aheads, int l) {
    int w = threadIdx.x >> 5, lane = threadIdx.x & 31;
    int row = blockIdx.x * 8 + w;          // b*NN + n
    int b = row >> 11, n = row & (NN - 1);
    #pragma unroll
    for (int h = 0; h < NH; h++) {
        float v  = g_Wh[(size_t)row * NF + h * NO + lane];
        float a1 = aheads[((size_t)l * NH + h) * 2 * NO + lane];
        float a2 = aheads[((size_t)l * NH + h) * 2 * NO + NO + lane];
        float p1 = v * a1, p2 = v * a2;
        #pragma unroll
        for (int off = 16; off; off >>= 1) {
            p1 += __shfl_xor_sync(0xffffffffu, p1, off);
            p2 += __shfl_xor_sync(0xffffffffu, p2, off);
        }
        if (lane == 0) {
            g_s1[(b * NH + h) * NN + n] = p1;
            g_s2[(b * NH + h) * NN + n] = p2;
        }
    }
}

// ---------------- s1/s2 for the single-head out stage -------------------------
__global__ void sout_kernel(const float* __restrict__ aout, int l) {
    int w = threadIdx.x >> 5, lane = threadIdx.x & 31;
    int row = blockIdx.x * 8 + w;          // b*NN + n
    float p1 = 0.f, p2 = 0.f;
    #pragma unroll
    for (int k = 0; k < NF / 32; k++) {
        float v = g_Wh[(size_t)row * NF + k * 32 + lane];
        p1 += v * aout[(size_t)l * 2 * NF + k * 32 + lane];
        p2 += v * aout[(size_t)l * 2 * NF + NF + k * 32 + lane];
    }
    #pragma unroll
    for (int off = 16; off; off >>= 1) {
        p1 += __shfl_xor_sync(0xffffffffu, p1, off);
        p2 += __shfl_xor_sync(0xffffffffu, p2, off);
    }
    if (lane == 0) { g_s1[row] = p1; g_s2[row] = p2; }
}

// ---------------- per-(b,head) max of s2 (softmax upper bound) ----------------
__global__ void m2_kernel() {
    int s = blockIdx.x;
    __shared__ float sm[256];
    float m = -3.0e38f;
    for (int i = threadIdx.x; i < NN; i += 256)
        m = fmaxf(m, g_s2[(size_t)s * NN + i]);
    sm[threadIdx.x] = m;
    __syncthreads();
    for (int off = 128; off; off >>= 1) {
        if (threadIdx.x < off)
            sm[threadIdx.x] = fmaxf(sm[threadIdx.x], sm[threadIdx.x + off]);
        __syncthreads();
    }
    if (threadIdx.x == 0) g_M2[s] = sm[0];
}

// ---------------- fused masked-softmax attention + P@V + elu -----------------
// grid (NN/32, 8, NB), block 256 (8 warps x 4 rows/warp, lane = output column)
// y = head (stage A) or o-chunk (stage B). V = g_Wh columns [y*32, y*32+32).
#define JT  128
#define RPW 4
#define AW  8

__global__ void attn_kernel(float* __restrict__ oext, int osel,
                            int spb, int symul, int elu2) {
    __shared__ __align__(16) float Vst[NO * JT];        // transposed, xor-swizzled float4s
    __shared__             float s2s[JT];
    __shared__ __align__(16) float ps[AW][RPW][32];

    float* out = (osel == 0) ? g_hA : (osel == 1 ? g_h : oext);
    int b = blockIdx.z, y = blockIdx.y;
    int w = threadIdx.x >> 5, lane = threadIdx.x & 31;
    int vb = y * NO;
    int sidx = b * spb + y * symul;
    const float* s1p = g_s1 + (size_t)sidx * NN;
    const float* s2p = g_s2 + (size_t)sidx * NN;
    float m2 = g_M2[sidx];
    int row0 = blockIdx.x * (AW * RPW) + w * RPW;

    float s1r[RPW], cir[RPW], acc[RPW], lsum[RPW];
    const unsigned* bmr[RPW];
    #pragma unroll
    for (int r = 0; r < RPW; r++) {
        s1r[r] = s1p[row0 + r];
        float t = s1r[r] + m2;
        cir[r] = fmaxf(t, 0.2f * t);       // upper bound on all masked logits
        acc[r] = 0.f; lsum[r] = 0.f;
        bmr[r] = g_bm + ((size_t)(b * NN + row0 + r) << 6);
    }
    const float* Vbase = g_Wh + vb;

    for (int jt = 0; jt < NN; jt += JT) {
        {   // load V tile transposed [o][j] with float4 xor-swizzle, + s2 tile
            int tid = threadIdx.x;
            #pragma unroll
            for (int pass = 0; pass < 4; pass++) {
                int idx = tid + pass * 256;
                int o = idx & 31, j4 = idx >> 5;        // j4 in 0..31
                int jg = jt + j4 * 4;
                float4 v;
                v.x = Vbase[(size_t)(b * NN + jg + 0) * NF + o];
                v.y = Vbase[(size_t)(b * NN + jg + 1) * NF + o];
                v.z = Vbase[(size_t)(b * NN + jg + 2) * NF + o];
                v.w = Vbase[(size_t)(b * NN + jg + 3) * NF + o];
                ((float4*)Vst)[o * 32 + (j4 ^ (o & 7))] = v;
            }
            if (tid < JT) s2s[tid] = s2p[jt + tid];
        }
        __syncthreads();

        #pragma unroll
        for (int c = 0; c < JT / 32; c++) {
            float s2v = s2s[c * 32 + lane];
            #pragma unroll
            for (int r = 0; r < RPW; r++) {
                unsigned mw = __ldg(&bmr[r][(jt >> 5) + c]);
                float x = s1r[r] + s2v;
                float e = fmaxf(x, 0.2f * x);           // leakyrelu(0.2)
                float p = ((mw >> lane) & 1u) ? __expf(e - cir[r]) : 0.f;
                lsum[r] += p;
                ps[w][r][lane] = p;
            }
            __syncwarp();
            #pragma unroll
            for (int k4 = 0; k4 < 8; k4++) {
                float4 vj = ((const float4*)Vst)[lane * 32 + ((c * 8 + k4) ^ (lane & 7))];
                #pragma unroll
                for (int r = 0; r < RPW; r++) {
                    float4 pk = *(const float4*)&ps[w][r][k4 * 4];
                    acc[r] += pk.x * vj.x + pk.y * vj.y + pk.z * vj.z + pk.w * vj.w;
                }
            }
            __syncwarp();
        }
        __syncthreads();
    }

    #pragma unroll
    for (int r = 0; r < RPW; r++) {
        float l = lsum[r];
        #pragma unroll
        for (int off = 16; off; off >>= 1)
            l += __shfl_xor_sync(0xffffffffu, l, off);
        float v = acc[r] / l;
        v = (v > 0.f) ? v : (__expf(v) - 1.f);          // elu
        if (elu2) v = (v > 0.f) ? v : (__expf(v) - 1.f); // second elu (out stage)
        out[(size_t)(b * NN + row0 + r) * NF + vb + lane] = v;
    }
}

// ---------------- launch ------------------------------------------------------
extern "C" void kernel_launch(void* const* d_in, const int* in_sizes, int n_in,
                              void* d_out, int out_size) {
    const float* x       = (const float*)d_in[0];
    const int*   adj     = (const int*)  d_in[1];
    const float* W_heads = (const float*)d_in[2];
    const float* a_heads = (const float*)d_in[3];
    const float* W_out   = (const float*)d_in[4];
    const float* a_out   = (const float*)d_in[5];
    float* out = (float*)d_out;

    bm_kernel<<<NB * NN * 64 / 8, 256>>>(adj);

    for (int l = 0; l < 3; l++) {
        // ---- stage A: 8-head GAT ----
        pack_kernel<<<NF, NF>>>(W_heads, l);
        gemm_kernel<<<dim3(4, NB * NN / 64), 256>>>(l == 0 ? x : nullptr, nullptr,
                                                    l == 0 ? 0 : 1, 0);
        sheads_kernel<<<NB * NN / 8, 256>>>(a_heads, l);
        m2_kernel<<<NB * NH, 256>>>();
        attn_kernel<<<dim3(NN / 32, 8, NB), 256>>>(nullptr, 0, NH, 1, 0);

        // ---- stage B: single-head out GAT (+extra elu) ----
        gemm_kernel<<<dim3(4, NB * NN / 64), 256>>>(nullptr,
                                                    W_out + (size_t)l * NF * NF,
                                                    2, 1);
        sout_kernel<<<NB * NN / 8, 256>>>(a_out, l);
        m2_kernel<<<NB, 256>>>();
        attn_kernel<<<dim3(NN / 32, 8, NB), 256>>>(l == 2 ? out : nullptr,
                                                   l == 2 ? 2 : 1, 1, 0, 1);
    }
}